// round 16
// baseline (speedup 1.0000x reference)
#include <cuda_runtime.h>
#include <cstdint>

#define N_ROWS 8192
#define N_COLS 50257
#define K_TOP  5734   // int(0.7 * 8192)
#define NW     8      // warps per 256-thread block

// Scratch (allocation-free per harness rules)
__device__ float    g_loss[N_ROWS];
__device__ unsigned g_count;   // zero at load; reset by last CTA every launch

// ---------------------------------------------------------------------------
// Fused kernel: one CTA per row computes loss[r] = logsumexp(row) - row[t];
// the LAST CTA to finish (threadfence-reduction pattern) then runs an O(n)
// radix threshold-select over the 8192 losses and writes the top-k mean.
//   - losses are strictly positive -> uint bits order-isomorphic to float
//   - per-warp privatized histograms + warp-aggregated atomics
//   - warp-parallel suffix scan of the 256 bins (R12's serial scan was ~16us)
// ---------------------------------------------------------------------------
__global__ __launch_bounds__(256) void fused_loss_topk(
    const float* __restrict__ input,
    const int* __restrict__ target,
    float* __restrict__ out)
{
    const int r    = blockIdx.x;
    const int tid  = threadIdx.x;
    const int lane = tid & 31;
    const int wid  = tid >> 5;
    const float* __restrict__ row = input + (size_t)r * (size_t)N_COLS;

    // ---------------- phase 1: row logsumexp (measured at DRAM floor) -------
    float s0 = 0.f, s1 = 0.f, s2 = 0.f, s3 = 0.f;

    const int mis  = (int)(((size_t)r * (size_t)N_COLS) & 3);  // 50257 % 4 == 1
    const int head = (4 - mis) & 3;

    if (tid < head) s0 += __expf(__ldcs(row + tid));

    const int nvec = (N_COLS - head) >> 2;
    const float4* __restrict__ v4 = (const float4*)(row + head);
    #pragma unroll 8
    for (int i = tid; i < nvec; i += 256) {
        float4 x = __ldcs(v4 + i);
        s0 += __expf(x.x);
        s1 += __expf(x.y);
        s2 += __expf(x.z);
        s3 += __expf(x.w);
    }
    const int tail_start = head + (nvec << 2);
    for (int i = tail_start + tid; i < N_COLS; i += 256)
        s0 += __expf(__ldcs(row + i));

    float s = (s0 + s1) + (s2 + s3);
    #pragma unroll
    for (int off = 16; off; off >>= 1)
        s += __shfl_down_sync(0xffffffffu, s, off);

    __shared__ float warp_s[NW];
    __shared__ int   s_last;
    if (lane == 0) warp_s[wid] = s;
    __syncthreads();

    if (tid == 0) {
        float tot = 0.f;
        #pragma unroll
        for (int w = 0; w < NW; ++w) tot += warp_s[w];
        int t = target[r];
        if (t < 0) t = 0;
        if (t >= N_COLS) t = N_COLS - 1;
        g_loss[r] = __logf(tot) - __ldg(row + t);   // > 0 always
        __threadfence();                            // publish before counting
        unsigned old = atomicAdd(&g_count, 1u);
        s_last = (old == N_ROWS - 1);
    }
    __syncthreads();
    if (!s_last) return;

    // ---------------- phase 2: last CTA does radix threshold-select --------
    if (tid == 0) g_count = 0;          // reset for next (graph-replayed) launch
    __threadfence();                     // all g_loss writes now visible

    __shared__ unsigned hist[NW][264];   // per-warp private, padded
    __shared__ unsigned s_prefix, s_need;

    unsigned prefix = 0, pmask = 0, need = K_TOP;

    #pragma unroll
    for (int shift = 24; shift >= 0; shift -= 8) {
        for (int i = tid; i < NW * 264; i += 256)
            ((unsigned*)hist)[i] = 0;
        __syncthreads();

        // 8192/256 = 32 uniform iterations -> full-mask warp ops are safe
        for (int i = tid; i < N_ROWS; i += 256) {
            const unsigned bv  = __float_as_uint(g_loss[i]);
            const bool part    = (bv & pmask) == prefix;
            const unsigned bin = part ? ((bv >> shift) & 0xFFu) : 256u;
            const unsigned m   = __match_any_sync(0xffffffffu, bin);
            if (part && lane == (__ffs(m) - 1))
                atomicAdd(&hist[wid][bin], (unsigned)__popc(m));
        }
        __syncthreads();

        // warp 0: merge private hists + warp-parallel descending suffix scan
        if (wid == 0) {
            unsigned local[8], lsum = 0;
            #pragma unroll
            for (int j = 0; j < 8; ++j) {
                unsigned c = 0;
                #pragma unroll
                for (int w = 0; w < NW; ++w) c += hist[w][lane * 8 + j];
                local[j] = c;
                lsum += c;
            }
            // inclusive suffix sum across lanes (sum over lanes >= this one)
            unsigned suff = lsum;
            #pragma unroll
            for (int off = 1; off < 32; off <<= 1) {
                unsigned o = __shfl_down_sync(0xffffffffu, suff, off);
                if (lane + off < 32) suff += o;
            }
            unsigned above = __shfl_down_sync(0xffffffffu, suff, 1); // lanes > this
            if (lane == 31) above = 0;

            // walk this lane's 8 bins high->low; exactly one lane/bin matches
            unsigned cum = above;
            #pragma unroll
            for (int j = 7; j >= 0; --j) {
                const unsigned c = local[j];
                if (cum < need && cum + c >= need) {
                    s_prefix = prefix | ((unsigned)(lane * 8 + j) << shift);
                    s_need   = need - cum;
                }
                cum += c;
            }
        }
        __syncthreads();
        prefix = s_prefix;
        need   = s_need;
        pmask |= (0xFFu << shift);
    }
    // prefix = exact bits of k-th largest; need = #ties to take at threshold

    float sum = 0.f;
    for (int i = tid; i < N_ROWS; i += 256) {
        const float x = g_loss[i];
        if (__float_as_uint(x) > prefix) sum += x;
    }
    #pragma unroll
    for (int off = 16; off; off >>= 1)
        sum += __shfl_down_sync(0xffffffffu, sum, off);

    __shared__ float s_part[NW];
    if (lane == 0) s_part[wid] = sum;
    __syncthreads();

    if (tid == 0) {
        float t = 0.f;
        #pragma unroll
        for (int w = 0; w < NW; ++w) t += s_part[w];
        out[0] = (t + (float)need * __uint_as_float(prefix)) / (float)K_TOP;
    }
}

// ---------------------------------------------------------------------------
extern "C" void kernel_launch(void* const* d_in, const int* in_sizes, int n_in,
                              void* d_out, int out_size)
{
    const float* input  = (const float*)d_in[0];   // [8192, 50257] fp32
    const int*   target = (const int*)d_in[1];     // [8192] int32 (proven R7)
    float* out = (float*)d_out;

    fused_loss_topk<<<N_ROWS, 256>>>(input, target, out);
}